// round 2
// baseline (speedup 1.0000x reference)
#include <cuda_runtime.h>
#include <cstdint>

#define S_LEN   2048
#define HEADS   12
#define BATCH   4
#define DHEAD   64
#define BT      64            // q rows per CTA
#define LDP     68            // padded smem row (floats)
#define NTHREADS 128

#define OUT_ELEMS  6291456LL        // 4*12*2048*64
#define W_ELEMS    201326592LL      // 4*12*2048*2048
#define SMEM_BYTES (4 * 64 * LDP * 4)

__device__ __forceinline__ uint32_t f2tf(float f) {
    uint32_t r;
    asm("cvt.rna.tf32.f32 %0, %1;\n" : "=r"(r) : "f"(f));
    return r;
}

__device__ __forceinline__ void mma_tf32(float* d,
                                         uint32_t a0, uint32_t a1, uint32_t a2, uint32_t a3,
                                         uint32_t b0, uint32_t b1) {
    asm volatile(
        "mma.sync.aligned.m16n8k8.row.col.f32.tf32.tf32.f32 "
        "{%0,%1,%2,%3}, {%4,%5,%6,%7}, {%8,%9}, {%0,%1,%2,%3};\n"
        : "+f"(d[0]), "+f"(d[1]), "+f"(d[2]), "+f"(d[3])
        : "r"(a0), "r"(a1), "r"(a2), "r"(a3), "r"(b0), "r"(b1));
}

// load a 64x64 fp32 tile (gmem row stride 2304) -> smem [64][LDP], tf32-rounded, scaled
__device__ __forceinline__ void load_tile(const float* __restrict__ g, float* sm, float mult) {
    int t = threadIdx.x;
#pragma unroll
    for (int i = 0; i < 8; i++) {
        int idx = t + i * NTHREADS;          // 0..1023
        int r   = idx >> 4;
        int c4  = (idx & 15) << 2;
        float4 v = *reinterpret_cast<const float4*>(g + (size_t)r * 2304 + c4);
        float* d = sm + r * LDP + c4;
        d[0] = __uint_as_float(f2tf(v.x * mult));
        d[1] = __uint_as_float(f2tf(v.y * mult));
        d[2] = __uint_as_float(f2tf(v.z * mult));
        d[3] = __uint_as_float(f2tf(v.w * mult));
    }
}

__global__ void __launch_bounds__(NTHREADS, 1)
attn_kernel(const float* __restrict__ x, float* __restrict__ o_out, float* __restrict__ w_out) {
    extern __shared__ float smem[];
    float* Qs = smem;
    float* Ks = Qs + 64 * LDP;
    float* Vs = Ks + 64 * LDP;
    float* Ps = Vs + 64 * LDP;

    const int bh = blockIdx.x;
    const int qb = blockIdx.y;
    const int b  = bh / HEADS;
    const int h  = bh % HEADS;
    const int q0 = qb * BT;

    const float* xb = x + (size_t)b * S_LEN * 2304 + h * 64;

    const int tid  = threadIdx.x;
    const int w    = tid >> 5;
    const int lane = tid & 31;
    const int ry   = lane >> 2;   // groupID
    const int tx   = lane & 3;    // threadID in group

    // Q tile, pre-scaled by 1/sqrt(64)=0.125
    load_tile(xb + (size_t)q0 * 2304, Qs, 0.125f);

    const int jd = qb;   // diagonal k-tile
    const int r_lo = q0 + w * 16 + ry;
    const int r_hi = r_lo + 8;

    float m0 = -1e30f, m1 = -1e30f, l0 = 0.f, l1 = 0.f;

    // ---------------- pass A: online softmax stats ----------------
    for (int j = 0; j <= jd; j++) {
        __syncthreads();
        load_tile(xb + 768 + (size_t)(j * 64) * 2304, Ks, 1.0f);
        __syncthreads();

        float s[8][4];
#pragma unroll
        for (int nt = 0; nt < 8; nt++)
            s[nt][0] = s[nt][1] = s[nt][2] = s[nt][3] = 0.f;

#pragma unroll
        for (int kk = 0; kk < 8; kk++) {
            const int kc = kk * 8;
            const float* qrow = Qs + (w * 16 + ry) * LDP + kc + tx;
            uint32_t a0 = __float_as_uint(qrow[0]);
            uint32_t a1 = __float_as_uint(qrow[8 * LDP]);
            uint32_t a2 = __float_as_uint(qrow[4]);
            uint32_t a3 = __float_as_uint(qrow[8 * LDP + 4]);
#pragma unroll
            for (int nt = 0; nt < 8; nt++) {
                const float* krow = Ks + (nt * 8 + ry) * LDP + kc + tx;
                mma_tf32(s[nt], a0, a1, a2, a3,
                         __float_as_uint(krow[0]), __float_as_uint(krow[4]));
            }
        }

        if (j == jd) {   // causal mask inside diag tile
#pragma unroll
            for (int nt = 0; nt < 8; nt++) {
#pragma unroll
                for (int c = 0; c < 2; c++) {
                    int col = j * 64 + nt * 8 + tx * 2 + c;
                    if (col > r_lo) s[nt][c]     = -1e30f;
                    if (col > r_hi) s[nt][2 + c] = -1e30f;
                }
            }
        }

        float tm0 = -1e30f, tm1 = -1e30f;
#pragma unroll
        for (int nt = 0; nt < 8; nt++) {
            tm0 = fmaxf(tm0, fmaxf(s[nt][0], s[nt][1]));
            tm1 = fmaxf(tm1, fmaxf(s[nt][2], s[nt][3]));
        }
        tm0 = fmaxf(tm0, __shfl_xor_sync(0xffffffffu, tm0, 1));
        tm0 = fmaxf(tm0, __shfl_xor_sync(0xffffffffu, tm0, 2));
        tm1 = fmaxf(tm1, __shfl_xor_sync(0xffffffffu, tm1, 1));
        tm1 = fmaxf(tm1, __shfl_xor_sync(0xffffffffu, tm1, 2));

        float mn0 = fmaxf(m0, tm0), mn1 = fmaxf(m1, tm1);
        float ts0 = 0.f, ts1 = 0.f;
#pragma unroll
        for (int nt = 0; nt < 8; nt++) {
            ts0 += __expf(s[nt][0] - mn0) + __expf(s[nt][1] - mn0);
            ts1 += __expf(s[nt][2] - mn1) + __expf(s[nt][3] - mn1);
        }
        ts0 += __shfl_xor_sync(0xffffffffu, ts0, 1);
        ts0 += __shfl_xor_sync(0xffffffffu, ts0, 2);
        ts1 += __shfl_xor_sync(0xffffffffu, ts1, 1);
        ts1 += __shfl_xor_sync(0xffffffffu, ts1, 2);

        l0 = l0 * __expf(m0 - mn0) + ts0;
        l1 = l1 * __expf(m1 - mn1) + ts1;
        m0 = mn0; m1 = mn1;
    }

    const float inv0 = 1.0f / l0;
    const float inv1 = 1.0f / l1;

    float o[8][4];
#pragma unroll
    for (int nt = 0; nt < 8; nt++)
        o[nt][0] = o[nt][1] = o[nt][2] = o[nt][3] = 0.f;

    float* Pw = Ps + (w * 16) * LDP;   // warp-private 16 rows

    // ---------------- pass B: recompute, write P, accumulate PV ----------------
    for (int j = 0; j <= jd; j++) {
        __syncthreads();
        load_tile(xb + 768  + (size_t)(j * 64) * 2304, Ks, 1.0f);
        load_tile(xb + 1536 + (size_t)(j * 64) * 2304, Vs, 1.0f);
        __syncthreads();

        float s[8][4];
#pragma unroll
        for (int nt = 0; nt < 8; nt++)
            s[nt][0] = s[nt][1] = s[nt][2] = s[nt][3] = 0.f;

#pragma unroll
        for (int kk = 0; kk < 8; kk++) {
            const int kc = kk * 8;
            const float* qrow = Qs + (w * 16 + ry) * LDP + kc + tx;
            uint32_t a0 = __float_as_uint(qrow[0]);
            uint32_t a1 = __float_as_uint(qrow[8 * LDP]);
            uint32_t a2 = __float_as_uint(qrow[4]);
            uint32_t a3 = __float_as_uint(qrow[8 * LDP + 4]);
#pragma unroll
            for (int nt = 0; nt < 8; nt++) {
                const float* krow = Ks + (nt * 8 + ry) * LDP + kc + tx;
                mma_tf32(s[nt], a0, a1, a2, a3,
                         __float_as_uint(krow[0]), __float_as_uint(krow[4]));
            }
        }

        if (j == jd) {
#pragma unroll
            for (int nt = 0; nt < 8; nt++) {
#pragma unroll
                for (int c = 0; c < 2; c++) {
                    int col = j * 64 + nt * 8 + tx * 2 + c;
                    if (col > r_lo) s[nt][c]     = -1e30f;
                    if (col > r_hi) s[nt][2 + c] = -1e30f;
                }
            }
        }

        // normalized probabilities -> warp-private smem
#pragma unroll
        for (int nt = 0; nt < 8; nt++) {
            float p0 = __expf(s[nt][0] - m0) * inv0;
            float p1 = __expf(s[nt][1] - m0) * inv0;
            float p2 = __expf(s[nt][2] - m1) * inv1;
            float p3 = __expf(s[nt][3] - m1) * inv1;
            float2* d0 = reinterpret_cast<float2*>(Pw + ry * LDP + nt * 8 + 2 * tx);
            float2* d1 = reinterpret_cast<float2*>(Pw + (ry + 8) * LDP + nt * 8 + 2 * tx);
            *d0 = make_float2(p0, p1);
            *d1 = make_float2(p2, p3);
        }
        __syncwarp();

        // stream P tile to attn_weights (evict-first: keep L2 for K/V)
        if (w_out) {
            size_t wb = ((size_t)bh * S_LEN + q0 + w * 16) * S_LEN + (size_t)j * 64;
#pragma unroll
            for (int i = 0; i < 8; i++) {
                int idx = i * 32 + lane;
                int r   = idx >> 4;
                int c4  = (idx & 15) << 2;
                float4 v = *reinterpret_cast<const float4*>(Pw + r * LDP + c4);
                __stcs(reinterpret_cast<float4*>(w_out + wb + (size_t)r * S_LEN + c4), v);
            }
        }

        // O += P @ V
#pragma unroll
        for (int kk = 0; kk < 8; kk++) {
            const int kc = kk * 8;
            const float* prow = Pw + ry * LDP + kc + tx;
            uint32_t a0 = f2tf(prow[0]);
            uint32_t a1 = f2tf(prow[8 * LDP]);
            uint32_t a2 = f2tf(prow[4]);
            uint32_t a3 = f2tf(prow[8 * LDP + 4]);
#pragma unroll
            for (int nt = 0; nt < 8; nt++) {
                uint32_t b0 = __float_as_uint(Vs[(kc + tx) * LDP + nt * 8 + ry]);
                uint32_t b1 = __float_as_uint(Vs[(kc + tx + 4) * LDP + nt * 8 + ry]);
                mma_tf32(o[nt], a0, a1, a2, a3, b0, b1);
            }
        }
    }

    // zero-fill the strictly-upper tiles of attn_weights
    if (w_out) {
        int col0 = (jd + 1) * 64;
        if (col0 < S_LEN) {
            int Wd4 = (S_LEN - col0) >> 2;
            size_t base = ((size_t)bh * S_LEN + q0) * S_LEN + col0;
            float4 z = make_float4(0.f, 0.f, 0.f, 0.f);
            for (int idx = tid; idx < 64 * Wd4; idx += NTHREADS) {
                int r = idx / Wd4;
                int c = idx - r * Wd4;
                __stcs(reinterpret_cast<float4*>(w_out + base + (size_t)r * S_LEN) + c, z);
            }
        }
    }

    // write attn_output
    if (o_out) {
        size_t ob = (size_t)bh * S_LEN * DHEAD;
#pragma unroll
        for (int nt = 0; nt < 8; nt++) {
            *reinterpret_cast<float2*>(o_out + ob + (size_t)r_lo * DHEAD + nt * 8 + 2 * tx) =
                make_float2(o[nt][0], o[nt][1]);
            *reinterpret_cast<float2*>(o_out + ob + (size_t)r_hi * DHEAD + nt * 8 + 2 * tx) =
                make_float2(o[nt][2], o[nt][3]);
        }
    }
}

extern "C" void kernel_launch(void* const* d_in, const int* in_sizes, int n_in,
                              void* d_out, int out_size) {
    const float* x = (const float*)d_in[0];
    float* out = (float*)d_out;

    float* o_ptr = nullptr;
    float* w_ptr = nullptr;
    if ((long long)out_size == OUT_ELEMS + W_ELEMS) { o_ptr = out; w_ptr = out + OUT_ELEMS; }
    else if ((long long)out_size == W_ELEMS)        { w_ptr = out; }
    else                                            { o_ptr = out; }

    cudaFuncSetAttribute(attn_kernel, cudaFuncAttributeMaxDynamicSharedMemorySize, SMEM_BYTES);

    dim3 grid(BATCH * HEADS, S_LEN / BT);
    attn_kernel<<<grid, NTHREADS, SMEM_BYTES>>>(x, o_ptr, w_ptr);
}

// round 3
// speedup vs baseline: 1.0105x; 1.0105x over previous
#include <cuda_runtime.h>
#include <cstdint>

#define S_LEN   2048
#define HEADS   12
#define BATCH   4
#define DHEAD   64
#define BT      64            // q rows per block
#define NQB     (S_LEN / BT)  // 32
#define LDP     68            // padded smem row (floats)
#define NTHREADS 128

#define OUT_ELEMS  6291456LL        // 4*12*2048*64
#define W_ELEMS    201326592LL      // 4*12*2048*2048
#define SMEM_BYTES (4 * 64 * LDP * 4)

__device__ __forceinline__ uint32_t f2tf(float f) {
    uint32_t r;
    asm("cvt.rna.tf32.f32 %0, %1;\n" : "=r"(r) : "f"(f));
    return r;
}

__device__ __forceinline__ void mma_tf32(float* d,
                                         uint32_t a0, uint32_t a1, uint32_t a2, uint32_t a3,
                                         uint32_t b0, uint32_t b1) {
    asm volatile(
        "mma.sync.aligned.m16n8k8.row.col.f32.tf32.tf32.f32 "
        "{%0,%1,%2,%3}, {%4,%5,%6,%7}, {%8,%9}, {%0,%1,%2,%3};\n"
        : "+f"(d[0]), "+f"(d[1]), "+f"(d[2]), "+f"(d[3])
        : "r"(a0), "r"(a1), "r"(a2), "r"(a3), "r"(b0), "r"(b1));
}

__device__ __forceinline__ void ldsm4(uint32_t& r0, uint32_t& r1, uint32_t& r2, uint32_t& r3,
                                      uint32_t addr) {
    asm volatile("ldmatrix.sync.aligned.m8n8.x4.shared.b16 {%0,%1,%2,%3}, [%4];\n"
                 : "=r"(r0), "=r"(r1), "=r"(r2), "=r"(r3) : "r"(addr));
}

// load a 64x64 fp32 tile (gmem row stride 2304) -> smem [64][LDP], tf32-rounded, scaled
__device__ __forceinline__ void load_tile(const float* __restrict__ g, float* sm, float mult) {
    int t = threadIdx.x;
#pragma unroll
    for (int i = 0; i < 8; i++) {
        int idx = t + i * NTHREADS;          // 0..1023
        int r   = idx >> 4;
        int c4  = (idx & 15) << 2;
        float4 v = *reinterpret_cast<const float4*>(g + (size_t)r * 2304 + c4);
        float* d = sm + r * LDP + c4;
        d[0] = __uint_as_float(f2tf(v.x * mult));
        d[1] = __uint_as_float(f2tf(v.y * mult));
        d[2] = __uint_as_float(f2tf(v.z * mult));
        d[3] = __uint_as_float(f2tf(v.w * mult));
    }
}

__global__ void __launch_bounds__(NTHREADS, 1)
attn_kernel(const float* __restrict__ x, float* __restrict__ o_out, float* __restrict__ w_out) {
    extern __shared__ float smem[];
    float* Qs = smem;
    float* Ks = Qs + 64 * LDP;
    float* Vs = Ks + 64 * LDP;
    float* Ps = Vs + 64 * LDP;

    const int bh  = blockIdx.x;
    const int qbx = blockIdx.y;
    const int b   = bh / HEADS;
    const int h   = bh % HEADS;

    const float* xb = x + (size_t)b * S_LEN * 2304 + h * 64;

    const int tid  = threadIdx.x;
    const int w    = tid >> 5;
    const int lane = tid & 31;
    const int ry   = lane >> 2;   // groupID
    const int tx   = lane & 3;    // threadID in group

    float* Pw = Ps + (w * 16) * LDP;   // warp-private 16 rows

    // ldmatrix lane base addresses (byte, shared space)
    const uint32_t shQ = (uint32_t)__cvta_generic_to_shared(Qs);
    const uint32_t shK = (uint32_t)__cvta_generic_to_shared(Ks);
    const uint32_t shP = (uint32_t)__cvta_generic_to_shared(Pw);

    // A-pattern (16x8 tile): m0 rows0-7/c0, m1 rows8-15/c0, m2 rows0-7/c4, m3 rows8-15/c4
    const int rA = (lane & 7) + (((lane >> 3) & 1) << 3);
    const int cA = ((lane >> 4) & 1) << 2;
    const uint32_t aQ = shQ + (uint32_t)(((w * 16 + rA) * LDP + cA) * 4);
    const uint32_t aP = shP + (uint32_t)((rA * LDP + cA) * 4);
    // B-pattern pair (two adjacent 8-row n-tiles): m0 nt/c0, m1 nt/c4, m2 nt+1/c0, m3 nt+1/c4
    const int rK = (lane & 7) + (((lane >> 4) & 1) << 3);
    const int cK = ((lane >> 3) & 1) << 2;

#pragma unroll 1
    for (int half = 0; half < 2; half++) {
        const int qb = half ? (NQB - 1 - qbx) : qbx;
        const int q0 = qb * BT;
        const int jd = qb;
        const int r_lo = q0 + w * 16 + ry;
        const int r_hi = r_lo + 8;

        __syncthreads();
        load_tile(xb + (size_t)q0 * 2304, Qs, 0.125f);   // Q pre-scaled by 1/sqrt(64)
        __syncthreads();

        // hoist Q fragments for the whole q-block (both passes)
        uint32_t qf[8][4];
#pragma unroll
        for (int kk = 0; kk < 8; kk++)
            ldsm4(qf[kk][0], qf[kk][1], qf[kk][2], qf[kk][3], aQ + kk * 32u);

        float m0 = -1e30f, m1 = -1e30f, l0 = 0.f, l1 = 0.f;

        // ---------------- pass A: online softmax stats ----------------
        for (int j = 0; j <= jd; j++) {
            __syncthreads();
            load_tile(xb + 768 + (size_t)(j * 64) * 2304, Ks, 1.0f);
            __syncthreads();

            float s[8][4];
#pragma unroll
            for (int nt = 0; nt < 8; nt++)
                s[nt][0] = s[nt][1] = s[nt][2] = s[nt][3] = 0.f;

#pragma unroll
            for (int kk = 0; kk < 8; kk++) {
#pragma unroll
                for (int ntp = 0; ntp < 4; ntp++) {
                    uint32_t b0, b1, b2, b3;
                    ldsm4(b0, b1, b2, b3,
                          shK + (uint32_t)(((ntp * 16 + rK) * LDP + kk * 8 + cK) * 4));
                    mma_tf32(s[2 * ntp],     qf[kk][0], qf[kk][1], qf[kk][2], qf[kk][3], b0, b1);
                    mma_tf32(s[2 * ntp + 1], qf[kk][0], qf[kk][1], qf[kk][2], qf[kk][3], b2, b3);
                }
            }

            if (j == jd) {   // causal mask inside diag tile
#pragma unroll
                for (int nt = 0; nt < 8; nt++) {
#pragma unroll
                    for (int c = 0; c < 2; c++) {
                        int col = j * 64 + nt * 8 + tx * 2 + c;
                        if (col > r_lo) s[nt][c]     = -1e30f;
                        if (col > r_hi) s[nt][2 + c] = -1e30f;
                    }
                }
            }

            float tm0 = -1e30f, tm1 = -1e30f;
#pragma unroll
            for (int nt = 0; nt < 8; nt++) {
                tm0 = fmaxf(tm0, fmaxf(s[nt][0], s[nt][1]));
                tm1 = fmaxf(tm1, fmaxf(s[nt][2], s[nt][3]));
            }
            tm0 = fmaxf(tm0, __shfl_xor_sync(0xffffffffu, tm0, 1));
            tm0 = fmaxf(tm0, __shfl_xor_sync(0xffffffffu, tm0, 2));
            tm1 = fmaxf(tm1, __shfl_xor_sync(0xffffffffu, tm1, 1));
            tm1 = fmaxf(tm1, __shfl_xor_sync(0xffffffffu, tm1, 2));

            float mn0 = fmaxf(m0, tm0), mn1 = fmaxf(m1, tm1);
            float ts0 = 0.f, ts1 = 0.f;
#pragma unroll
            for (int nt = 0; nt < 8; nt++) {
                ts0 += __expf(s[nt][0] - mn0) + __expf(s[nt][1] - mn0);
                ts1 += __expf(s[nt][2] - mn1) + __expf(s[nt][3] - mn1);
            }
            ts0 += __shfl_xor_sync(0xffffffffu, ts0, 1);
            ts0 += __shfl_xor_sync(0xffffffffu, ts0, 2);
            ts1 += __shfl_xor_sync(0xffffffffu, ts1, 1);
            ts1 += __shfl_xor_sync(0xffffffffu, ts1, 2);

            l0 = l0 * __expf(m0 - mn0) + ts0;
            l1 = l1 * __expf(m1 - mn1) + ts1;
            m0 = mn0; m1 = mn1;
        }

        const float inv0 = 1.0f / l0;
        const float inv1 = 1.0f / l1;

        float o[8][4];
#pragma unroll
        for (int nt = 0; nt < 8; nt++)
            o[nt][0] = o[nt][1] = o[nt][2] = o[nt][3] = 0.f;

        // ---------------- pass B: recompute, write P, accumulate PV ----------------
        for (int j = 0; j <= jd; j++) {
            __syncthreads();
            load_tile(xb + 768  + (size_t)(j * 64) * 2304, Ks, 1.0f);
            load_tile(xb + 1536 + (size_t)(j * 64) * 2304, Vs, 1.0f);
            __syncthreads();

            float s[8][4];
#pragma unroll
            for (int nt = 0; nt < 8; nt++)
                s[nt][0] = s[nt][1] = s[nt][2] = s[nt][3] = 0.f;

#pragma unroll
            for (int kk = 0; kk < 8; kk++) {
#pragma unroll
                for (int ntp = 0; ntp < 4; ntp++) {
                    uint32_t b0, b1, b2, b3;
                    ldsm4(b0, b1, b2, b3,
                          shK + (uint32_t)(((ntp * 16 + rK) * LDP + kk * 8 + cK) * 4));
                    mma_tf32(s[2 * ntp],     qf[kk][0], qf[kk][1], qf[kk][2], qf[kk][3], b0, b1);
                    mma_tf32(s[2 * ntp + 1], qf[kk][0], qf[kk][1], qf[kk][2], qf[kk][3], b2, b3);
                }
            }

            if (j == jd) {
#pragma unroll
                for (int nt = 0; nt < 8; nt++) {
#pragma unroll
                    for (int c = 0; c < 2; c++) {
                        int col = j * 64 + nt * 8 + tx * 2 + c;
                        if (col > r_lo) s[nt][c]     = -1e30f;
                        if (col > r_hi) s[nt][2 + c] = -1e30f;
                    }
                }
            }

            // normalized probabilities -> warp-private smem
#pragma unroll
            for (int nt = 0; nt < 8; nt++) {
                float p0 = __expf(s[nt][0] - m0) * inv0;
                float p1 = __expf(s[nt][1] - m0) * inv0;
                float p2 = __expf(s[nt][2] - m1) * inv1;
                float p3 = __expf(s[nt][3] - m1) * inv1;
                float2* d0 = reinterpret_cast<float2*>(Pw + ry * LDP + nt * 8 + 2 * tx);
                float2* d1 = reinterpret_cast<float2*>(Pw + (ry + 8) * LDP + nt * 8 + 2 * tx);
                *d0 = make_float2(p0, p1);
                *d1 = make_float2(p2, p3);
            }
            __syncwarp();

            // stream P tile to attn_weights (evict-first: keep L2 for K/V)
            if (w_out) {
                size_t wb = ((size_t)bh * S_LEN + q0 + w * 16) * S_LEN + (size_t)j * 64;
#pragma unroll
                for (int i = 0; i < 8; i++) {
                    int idx = i * 32 + lane;
                    int r   = idx >> 4;
                    int c4  = (idx & 15) << 2;
                    float4 v = *reinterpret_cast<const float4*>(Pw + r * LDP + c4);
                    __stcs(reinterpret_cast<float4*>(w_out + wb + (size_t)r * S_LEN + c4), v);
                }
            }

            // O += P @ V
#pragma unroll
            for (int kk = 0; kk < 8; kk++) {
                const int kc = kk * 8;
                uint32_t p0, p1, p2, p3;
                ldsm4(p0, p1, p2, p3, aP + kk * 32u);
                uint32_t a0 = f2tf(__uint_as_float(p0));
                uint32_t a1 = f2tf(__uint_as_float(p1));
                uint32_t a2 = f2tf(__uint_as_float(p2));
                uint32_t a3 = f2tf(__uint_as_float(p3));
#pragma unroll
                for (int nt = 0; nt < 8; nt++) {
                    uint32_t b0 = __float_as_uint(Vs[(kc + tx) * LDP + nt * 8 + ry]);
                    uint32_t b1 = __float_as_uint(Vs[(kc + tx + 4) * LDP + nt * 8 + ry]);
                    mma_tf32(o[nt], a0, a1, a2, a3, b0, b1);
                }
            }
        }

        // zero-fill the strictly-upper tiles of attn_weights
        if (w_out) {
            int col0 = (jd + 1) * 64;
            if (col0 < S_LEN) {
                int Wd4 = (S_LEN - col0) >> 2;
                size_t base = ((size_t)bh * S_LEN + q0) * S_LEN + col0;
                float4 z = make_float4(0.f, 0.f, 0.f, 0.f);
                for (int idx = tid; idx < 64 * Wd4; idx += NTHREADS) {
                    int r = idx / Wd4;
                    int c = idx - r * Wd4;
                    __stcs(reinterpret_cast<float4*>(w_out + base + (size_t)r * S_LEN) + c, z);
                }
            }
        }

        // write attn_output
        if (o_out) {
            size_t ob = (size_t)bh * S_LEN * DHEAD;
#pragma unroll
            for (int nt = 0; nt < 8; nt++) {
                *reinterpret_cast<float2*>(o_out + ob + (size_t)r_lo * DHEAD + nt * 8 + 2 * tx) =
                    make_float2(o[nt][0], o[nt][1]);
                *reinterpret_cast<float2*>(o_out + ob + (size_t)r_hi * DHEAD + nt * 8 + 2 * tx) =
                    make_float2(o[nt][2], o[nt][3]);
            }
        }
    }
}

extern "C" void kernel_launch(void* const* d_in, const int* in_sizes, int n_in,
                              void* d_out, int out_size) {
    const float* x = (const float*)d_in[0];
    float* out = (float*)d_out;

    float* o_ptr = nullptr;
    float* w_ptr = nullptr;
    if ((long long)out_size == OUT_ELEMS + W_ELEMS) { o_ptr = out; w_ptr = out + OUT_ELEMS; }
    else if ((long long)out_size == W_ELEMS)        { w_ptr = out; }
    else                                            { o_ptr = out; }

    cudaFuncSetAttribute(attn_kernel, cudaFuncAttributeMaxDynamicSharedMemorySize, SMEM_BYTES);

    dim3 grid(BATCH * HEADS, NQB / 2);
    attn_kernel<<<grid, NTHREADS, SMEM_BYTES>>>(x, o_ptr, w_ptr);
}